// round 6
// baseline (speedup 1.0000x reference)
#include <cuda_runtime.h>

// OrdLoss: sum over valid voxels of [k<=t]*log(clip(p)) + [k>t]*log(clip(1-p)),
// divided by -count(valid). pred [N,C,D,H,W] f32, target replicated over C
// (read channel 0 only), mask [N,1,D,H,W] i32.
//
//  * select elimination:  (k<=t)? p : 1-p  ==  |saturate(k-t) - p|   (exact,
//    p in [0,1)). FADD.SAT (imm form) + FADD + FMAX(|src|) = 3 ops/element
//    vs ISETP+FADD+FSEL+FMAX = 4. Kernel is issue-limited (R5 ncu: issue 23%,
//    DRAM pinned 52% across occupancies) -> fewer ops = time.
//  * mask folded into clip floor: c_v = valid ? 1e-8 : 1.0 -> invalid voxels
//    contribute log(1)=0 exactly, no extra select.
//  * product across 4 voxels per channel (>=1e-32, no underflow), one __logf
//    per channel.
//  * __ldcs streaming loads for pred (zero reuse).
//  * 32 regs / 8 blocks/SM, grid fully resident; single kernel with
//    last-block-done deterministic final reduction.

#define N_      2
#define C_      16
#define MSP     (32 * 128 * 128)      // 524288 voxels per batch item
#define NVOX    (N_ * MSP)            // 1048576
#define NGROUPS (NVOX / 4)            // 262144 float4 groups
#define BLOCKS  1024
#define THREADS 256
// BLOCKS*THREADS == NGROUPS exactly

__device__ float g_partial[BLOCKS];
__device__ int   g_count[BLOCKS];
__device__ unsigned int g_ticket = 0;

__global__ void __launch_bounds__(THREADS, 8)
ord_loss_fused(const float* __restrict__ pred,
               const int*   __restrict__ target,
               const int*   __restrict__ mask,
               float*       __restrict__ out)
{
    const int g = blockIdx.x * THREADS + threadIdx.x;  // group of 4 voxels
    const int m = g * 4;
    const int n = m >> 19;                              // MSP == 2^19
    const int base = m + n * (C_ - 1) * MSP;            // n*C*MSP + spatial

    const int4 mk = *reinterpret_cast<const int4*>(mask + m);
    const int4 tg = *reinterpret_cast<const int4*>(target + base);

    // negated float targets: bias_k = saturate(k + nt)
    const float nt0 = -(float)tg.x;
    const float nt1 = -(float)tg.y;
    const float nt2 = -(float)tg.z;
    const float nt3 = -(float)tg.w;

    // mask folded into per-voxel clip floor: invalid -> floor 1.0 -> log 0
    const float c0 = (mk.x > 0) ? 1e-8f : 1.0f;
    const float c1 = (mk.y > 0) ? 1e-8f : 1.0f;
    const float c2 = (mk.z > 0) ? 1e-8f : 1.0f;
    const float c3 = (mk.w > 0) ? 1e-8f : 1.0f;
    int cnt = (mk.x > 0) + (mk.y > 0) + (mk.z > 0) + (mk.w > 0);

    float acc = 0.0f;

#pragma unroll
    for (int k = 0; k < C_; ++k) {
        const float4 p = __ldcs(reinterpret_cast<const float4*>(pred + base + k * MSP));
        const float kf = (float)k;                       // unrolled immediate
        // bias = 0 when k<=t, 1 when k>t; q = |bias - p| = p or 1-p (exact)
        const float q0 = fmaxf(fabsf(__saturatef(kf + nt0) - p.x), c0);
        const float q1 = fmaxf(fabsf(__saturatef(kf + nt1) - p.y), c1);
        const float q2 = fmaxf(fabsf(__saturatef(kf + nt2) - p.z), c2);
        const float q3 = fmaxf(fabsf(__saturatef(kf + nt3) - p.w), c3);
        acc += __logf((q0 * q1) * (q2 * q3));            // product >= 1e-32
    }

    float a = acc;

    // ---- warp reduce ----
#pragma unroll
    for (int off = 16; off > 0; off >>= 1) {
        a   += __shfl_xor_sync(0xFFFFFFFFu, a, off);
        cnt += __shfl_xor_sync(0xFFFFFFFFu, cnt, off);
    }

    __shared__ float sa[THREADS / 32];
    __shared__ int   sc[THREADS / 32];
    __shared__ bool  s_last;
    const int wid = threadIdx.x >> 5;
    const int lid = threadIdx.x & 31;
    if (lid == 0) { sa[wid] = a; sc[wid] = cnt; }
    __syncthreads();

    if (threadIdx.x == 0) {
        float aa = sa[0] + sa[1] + sa[2] + sa[3] + sa[4] + sa[5] + sa[6] + sa[7];
        int   cc = sc[0] + sc[1] + sc[2] + sc[3] + sc[4] + sc[5] + sc[6] + sc[7];
        g_partial[blockIdx.x] = aa;
        g_count[blockIdx.x]   = cc;
        __threadfence();
        unsigned int old = atomicAdd(&g_ticket, 1u);
        s_last = (old == BLOCKS - 1);
    }
    __syncthreads();

    if (!s_last) return;

    // ---- last block: final reduction over 1024 partials, fixed order ----
    float s = 0.0f;
    int   c = 0;
#pragma unroll
    for (int i = 0; i < BLOCKS / THREADS; ++i) {
        const int idx = threadIdx.x + i * THREADS;
        s += g_partial[idx];
        c += g_count[idx];
    }
#pragma unroll
    for (int off = 16; off > 0; off >>= 1) {
        s += __shfl_xor_sync(0xFFFFFFFFu, s, off);
        c += __shfl_xor_sync(0xFFFFFFFFu, c, off);
    }
    __shared__ float fa[THREADS / 32];
    __shared__ int   fc[THREADS / 32];
    if (lid == 0) { fa[wid] = s; fc[wid] = c; }
    __syncthreads();
    if (threadIdx.x == 0) {
        float ss = fa[0] + fa[1] + fa[2] + fa[3] + fa[4] + fa[5] + fa[6] + fa[7];
        int   cc = fc[0] + fc[1] + fc[2] + fc[3] + fc[4] + fc[5] + fc[6] + fc[7];
        out[0] = -ss / (float)cc;
        g_ticket = 0;   // reset for next graph replay
    }
}

extern "C" void kernel_launch(void* const* d_in, const int* in_sizes, int n_in,
                              void* d_out, int out_size)
{
    const float* pred   = (const float*)d_in[0];
    const int*   target = (const int*)d_in[1];
    const int*   mask   = (const int*)d_in[2];
    float*       out    = (float*)d_out;

    ord_loss_fused<<<BLOCKS, THREADS>>>(pred, target, mask, out);
}

// round 7
// speedup vs baseline: 1.0074x; 1.0074x over previous
#include <cuda_runtime.h>

// OrdLoss: sum over valid voxels of [k<=t]*log(clip(p)) + [k>t]*log(clip(1-p)),
// divided by -count(valid). pred [N,C,D,H,W] f32, target replicated over C
// (read channel 0 only), mask [N,1,D,H,W] i32.
//
//  * select elimination:  (k<=t)? p : 1-p  ==  |saturate(k-t) - p| (exact).
//  * mask folded into clip floor: c_v = valid ? 1e-8 : 1.0 -> log(1)=0.
//  * product across 4 voxels per channel (>=1e-32), one __logf per group.
//  * TWO independent groups per thread (same spatial voxel, batch 0 and
//    batch 1), interleaved chains -> 2x per-warp MLP. R6 was latency-bound
//    (issue 23%, occ 80%, DRAM pinned 59%): single chain per thread.
//  * 512 blocks, __launch_bounds__(256,5) (<=48 regs): 5 blocks/SM -> 740
//    resident >= 512 -> still one wave. Half the epilogues/fences.
//  * single kernel, last-block-done deterministic final reduction.

#define N_      2
#define C_      16
#define MSP     (32 * 128 * 128)      // 524288 voxels per batch item
#define NVOX    (N_ * MSP)            // 1048576
#define BLOCKS  512
#define THREADS 256
// BLOCKS*THREADS = 131072 threads = MSP/4 groups per batch; each thread
// handles spatial group m..m+3 in batch 0 AND batch 1.

__device__ float g_partial[BLOCKS];
__device__ int   g_count[BLOCKS];
__device__ unsigned int g_ticket = 0;

__global__ void __launch_bounds__(THREADS, 5)
ord_loss_fused(const float* __restrict__ pred,
               const int*   __restrict__ target,
               const int*   __restrict__ mask,
               float*       __restrict__ out)
{
    const int g = blockIdx.x * THREADS + threadIdx.x;   // spatial group in batch 0
    const int m = g * 4;                                 // spatial voxel index
    const int baseA = m;                                 // batch0, channel0
    const int baseB = m + C_ * MSP;                      // batch1, channel0

    const int4 mkA = *reinterpret_cast<const int4*>(mask + m);
    const int4 mkB = *reinterpret_cast<const int4*>(mask + m + MSP);
    const int4 tgA = *reinterpret_cast<const int4*>(target + baseA);
    const int4 tgB = *reinterpret_cast<const int4*>(target + baseB);

    // negated float targets: bias_k = saturate(k + nt)
    const float na0 = -(float)tgA.x, na1 = -(float)tgA.y,
                na2 = -(float)tgA.z, na3 = -(float)tgA.w;
    const float nb0 = -(float)tgB.x, nb1 = -(float)tgB.y,
                nb2 = -(float)tgB.z, nb3 = -(float)tgB.w;

    // mask folded into per-voxel clip floor
    const float ca0 = (mkA.x > 0) ? 1e-8f : 1.0f;
    const float ca1 = (mkA.y > 0) ? 1e-8f : 1.0f;
    const float ca2 = (mkA.z > 0) ? 1e-8f : 1.0f;
    const float ca3 = (mkA.w > 0) ? 1e-8f : 1.0f;
    const float cb0 = (mkB.x > 0) ? 1e-8f : 1.0f;
    const float cb1 = (mkB.y > 0) ? 1e-8f : 1.0f;
    const float cb2 = (mkB.z > 0) ? 1e-8f : 1.0f;
    const float cb3 = (mkB.w > 0) ? 1e-8f : 1.0f;
    int cnt = (mkA.x > 0) + (mkA.y > 0) + (mkA.z > 0) + (mkA.w > 0)
            + (mkB.x > 0) + (mkB.y > 0) + (mkB.z > 0) + (mkB.w > 0);

    float accA = 0.0f, accB = 0.0f;

#pragma unroll
    for (int k = 0; k < C_; ++k) {
        const float4 pA = __ldcs(reinterpret_cast<const float4*>(pred + baseA + k * MSP));
        const float4 pB = __ldcs(reinterpret_cast<const float4*>(pred + baseB + k * MSP));
        const float kf = (float)k;                        // unrolled immediate
        const float qa0 = fmaxf(fabsf(__saturatef(kf + na0) - pA.x), ca0);
        const float qa1 = fmaxf(fabsf(__saturatef(kf + na1) - pA.y), ca1);
        const float qa2 = fmaxf(fabsf(__saturatef(kf + na2) - pA.z), ca2);
        const float qa3 = fmaxf(fabsf(__saturatef(kf + na3) - pA.w), ca3);
        const float qb0 = fmaxf(fabsf(__saturatef(kf + nb0) - pB.x), cb0);
        const float qb1 = fmaxf(fabsf(__saturatef(kf + nb1) - pB.y), cb1);
        const float qb2 = fmaxf(fabsf(__saturatef(kf + nb2) - pB.z), cb2);
        const float qb3 = fmaxf(fabsf(__saturatef(kf + nb3) - pB.w), cb3);
        accA += __logf((qa0 * qa1) * (qa2 * qa3));        // products >= 1e-32
        accB += __logf((qb0 * qb1) * (qb2 * qb3));
    }

    float a = accA + accB;

    // ---- warp reduce ----
#pragma unroll
    for (int off = 16; off > 0; off >>= 1) {
        a   += __shfl_xor_sync(0xFFFFFFFFu, a, off);
        cnt += __shfl_xor_sync(0xFFFFFFFFu, cnt, off);
    }

    __shared__ float sa[THREADS / 32];
    __shared__ int   sc[THREADS / 32];
    __shared__ bool  s_last;
    const int wid = threadIdx.x >> 5;
    const int lid = threadIdx.x & 31;
    if (lid == 0) { sa[wid] = a; sc[wid] = cnt; }
    __syncthreads();

    if (threadIdx.x == 0) {
        float aa = sa[0] + sa[1] + sa[2] + sa[3] + sa[4] + sa[5] + sa[6] + sa[7];
        int   cc = sc[0] + sc[1] + sc[2] + sc[3] + sc[4] + sc[5] + sc[6] + sc[7];
        g_partial[blockIdx.x] = aa;
        g_count[blockIdx.x]   = cc;
        __threadfence();
        unsigned int old = atomicAdd(&g_ticket, 1u);
        s_last = (old == BLOCKS - 1);
    }
    __syncthreads();

    if (!s_last) return;

    // ---- last block: final reduction over 512 partials, fixed order ----
    float s = 0.0f;
    int   c = 0;
#pragma unroll
    for (int i = 0; i < BLOCKS / THREADS; ++i) {          // 2 per thread
        const int idx = threadIdx.x + i * THREADS;
        s += g_partial[idx];
        c += g_count[idx];
    }
#pragma unroll
    for (int off = 16; off > 0; off >>= 1) {
        s += __shfl_xor_sync(0xFFFFFFFFu, s, off);
        c += __shfl_xor_sync(0xFFFFFFFFu, c, off);
    }
    __shared__ float fa[THREADS / 32];
    __shared__ int   fc[THREADS / 32];
    if (lid == 0) { fa[wid] = s; fc[wid] = c; }
    __syncthreads();
    if (threadIdx.x == 0) {
        float ss = fa[0] + fa[1] + fa[2] + fa[3] + fa[4] + fa[5] + fa[6] + fa[7];
        int   cc = fc[0] + fc[1] + fc[2] + fc[3] + fc[4] + fc[5] + fc[6] + fc[7];
        out[0] = -ss / (float)cc;
        g_ticket = 0;   // reset for next graph replay
    }
}

extern "C" void kernel_launch(void* const* d_in, const int* in_sizes, int n_in,
                              void* d_out, int out_size)
{
    const float* pred   = (const float*)d_in[0];
    const int*   target = (const int*)d_in[1];
    const int*   mask   = (const int*)d_in[2];
    float*       out    = (float*)d_out;

    ord_loss_fused<<<BLOCKS, THREADS>>>(pred, target, mask, out);
}

// round 8
// speedup vs baseline: 1.0200x; 1.0125x over previous
#include <cuda_runtime.h>

// OrdLoss: sum over valid voxels of [k<=t]*log(clip(p)) + [k>t]*log(clip(1-p)),
// divided by -count(valid). pred [N,C,D,H,W] f32, target replicated over C
// (read channel 0 only), mask [N,1,D,H,W] i32.
//
//  * select elimination:  (k<=t)? p : 1-p  ==  |saturate(k-t) - p| (exact).
//  * mask folded into clip floor: c_v = valid ? 1e-8 : 1.0 -> log(1)=0.
//  * product across 4 voxels per channel (>=1e-32), one __logf per channel.
//  * explicit 1-ahead load pipeline: channel k+1 in flight during k's chain.
//  * epilogue uses st.release.gpu + atom.acq_rel ticket instead of
//    __threadfence(): gpu-scope threadfence emits CCTL.IVALL (full L1D flush)
//    on every finishing block -- 1024 flushes perturbing resident blocks.
//    Release stores are L2-visible with no flush. Last block reads partials
//    with __ldcg (cold lines -> L2 -> correct).
//  * __launch_bounds__(256,7): 7 blocks/SM x 148 = 1036 >= 1024 blocks ->
//    single wave at ~36 regs (scheduling freedom vs 32).

#define N_      2
#define C_      16
#define MSP     (32 * 128 * 128)      // 524288 voxels per batch item
#define NVOX    (N_ * MSP)            // 1048576
#define NGROUPS (NVOX / 4)            // 262144 float4 groups
#define BLOCKS  1024
#define THREADS 256
// BLOCKS*THREADS == NGROUPS exactly

__device__ float g_partial[BLOCKS];
__device__ int   g_count[BLOCKS];
__device__ unsigned int g_ticket = 0;

__global__ void __launch_bounds__(THREADS, 7)
ord_loss_fused(const float* __restrict__ pred,
               const int*   __restrict__ target,
               const int*   __restrict__ mask,
               float*       __restrict__ out)
{
    const int g = blockIdx.x * THREADS + threadIdx.x;  // group of 4 voxels
    const int m = g * 4;
    const int n = m >> 19;                              // MSP == 2^19
    const int base = m + n * (C_ - 1) * MSP;            // n*C*MSP + spatial

    const int4 mk = *reinterpret_cast<const int4*>(mask + m);
    const int4 tg = *reinterpret_cast<const int4*>(target + base);

    // negated float targets: bias_k = saturate(k + nt)
    const float nt0 = -(float)tg.x;
    const float nt1 = -(float)tg.y;
    const float nt2 = -(float)tg.z;
    const float nt3 = -(float)tg.w;

    // mask folded into per-voxel clip floor: invalid -> floor 1.0 -> log 0
    const float c0 = (mk.x > 0) ? 1e-8f : 1.0f;
    const float c1 = (mk.y > 0) ? 1e-8f : 1.0f;
    const float c2 = (mk.z > 0) ? 1e-8f : 1.0f;
    const float c3 = (mk.w > 0) ? 1e-8f : 1.0f;
    int cnt = (mk.x > 0) + (mk.y > 0) + (mk.z > 0) + (mk.w > 0);

    float acc = 0.0f;

    // ---- 1-ahead software-pipelined channel loop ----
    float4 cur = __ldcs(reinterpret_cast<const float4*>(pred + base));
#pragma unroll
    for (int k = 0; k < C_; ++k) {
        float4 nxt;
        if (k + 1 < C_)
            nxt = __ldcs(reinterpret_cast<const float4*>(pred + base + (k + 1) * MSP));
        const float kf = (float)k;                       // unrolled immediate
        // bias = 0 when k<=t, 1 when k>t; q = |bias - p| = p or 1-p (exact)
        const float q0 = fmaxf(fabsf(__saturatef(kf + nt0) - cur.x), c0);
        const float q1 = fmaxf(fabsf(__saturatef(kf + nt1) - cur.y), c1);
        const float q2 = fmaxf(fabsf(__saturatef(kf + nt2) - cur.z), c2);
        const float q3 = fmaxf(fabsf(__saturatef(kf + nt3) - cur.w), c3);
        acc += __logf((q0 * q1) * (q2 * q3));            // product >= 1e-32
        cur = nxt;
    }

    float a = acc;

    // ---- warp reduce ----
#pragma unroll
    for (int off = 16; off > 0; off >>= 1) {
        a   += __shfl_xor_sync(0xFFFFFFFFu, a, off);
        cnt += __shfl_xor_sync(0xFFFFFFFFu, cnt, off);
    }

    __shared__ float sa[THREADS / 32];
    __shared__ int   sc[THREADS / 32];
    __shared__ bool  s_last;
    const int wid = threadIdx.x >> 5;
    const int lid = threadIdx.x & 31;
    if (lid == 0) { sa[wid] = a; sc[wid] = cnt; }
    __syncthreads();

    if (threadIdx.x == 0) {
        float aa = sa[0] + sa[1] + sa[2] + sa[3] + sa[4] + sa[5] + sa[6] + sa[7];
        int   cc = sc[0] + sc[1] + sc[2] + sc[3] + sc[4] + sc[5] + sc[6] + sc[7];
        // release stores: visible at GPU scope before the acq_rel ticket bump,
        // NO CCTL.IVALL L1 flush (unlike __threadfence()).
        asm volatile("st.release.gpu.global.f32 [%0], %1;"
                     :: "l"(&g_partial[blockIdx.x]), "f"(aa) : "memory");
        asm volatile("st.release.gpu.global.b32 [%0], %1;"
                     :: "l"(&g_count[blockIdx.x]), "r"(cc) : "memory");
        unsigned int old;
        asm volatile("atom.acq_rel.gpu.global.add.u32 %0, [%1], %2;"
                     : "=r"(old) : "l"(&g_ticket), "r"(1u) : "memory");
        s_last = (old == BLOCKS - 1);
    }
    __syncthreads();

    if (!s_last) return;

    // ---- last block: final reduction over 1024 partials, fixed order ----
    // __ldcg: bypass L1 (lines are cold here anyway) -> read released values.
    float s = 0.0f;
    int   c = 0;
#pragma unroll
    for (int i = 0; i < BLOCKS / THREADS; ++i) {
        const int idx = threadIdx.x + i * THREADS;
        s += __ldcg(&g_partial[idx]);
        c += __ldcg(&g_count[idx]);
    }
#pragma unroll
    for (int off = 16; off > 0; off >>= 1) {
        s += __shfl_xor_sync(0xFFFFFFFFu, s, off);
        c += __shfl_xor_sync(0xFFFFFFFFu, c, off);
    }
    __shared__ float fa[THREADS / 32];
    __shared__ int   fc[THREADS / 32];
    if (lid == 0) { fa[wid] = s; fc[wid] = c; }
    __syncthreads();
    if (threadIdx.x == 0) {
        float ss = fa[0] + fa[1] + fa[2] + fa[3] + fa[4] + fa[5] + fa[6] + fa[7];
        int   cc = fc[0] + fc[1] + fc[2] + fc[3] + fc[4] + fc[5] + fc[6] + fc[7];
        out[0] = -ss / (float)cc;
        g_ticket = 0;   // reset for next graph replay
    }
}

extern "C" void kernel_launch(void* const* d_in, const int* in_sizes, int n_in,
                              void* d_out, int out_size)
{
    const float* pred   = (const float*)d_in[0];
    const int*   target = (const int*)d_in[1];
    const int*   mask   = (const int*)d_in[2];
    float*       out    = (float*)d_out;

    ord_loss_fused<<<BLOCKS, THREADS>>>(pred, target, mask, out);
}

// round 9
// speedup vs baseline: 1.0226x; 1.0025x over previous
#include <cuda_runtime.h>
#include <cstdint>

// OrdLoss: sum over valid voxels of [k<=t]*log(clip(p)) + [k>t]*log(clip(1-p)),
// divided by -count(valid). pred [N,C,D,H,W] f32, target replicated over C
// (read channel 0 only), mask [N,1,D,H,W] i32.
//
// R9 structural change: pred is streamed through SMEM with cp.async.cg
// (LDGSTS). In-flight loads cost ZERO registers (R2..R8 proved the 32-reg
// budget caps per-warp MLP at ~2 LDG.128 -> DRAM pinned ~53%). 4-slot
// per-thread ring, commit-group ordering -- no __syncthreads in the loop
// (each thread consumes exactly the 16B it issued).
//
//  * select elimination:  (k<=t)? p : 1-p  ==  |saturate(k-t) - p| (exact).
//  * mask folded into clip floor: c_v = valid ? 1e-8 : 1.0 -> log(1)=0.
//  * product across 4 voxels per channel (>=1e-32), one __logf per channel.
//  * epilogue: st.release.gpu partials + atom.acq_rel ticket (no CCTL.IVALL).

#define N_      2
#define C_      16
#define MSP     (32 * 128 * 128)      // 524288 voxels per batch item
#define NVOX    (N_ * MSP)            // 1048576
#define NGROUPS (NVOX / 4)            // 262144 float4 groups
#define BLOCKS  1024
#define THREADS 256
#define STAGES  4
// BLOCKS*THREADS == NGROUPS exactly

__device__ float g_partial[BLOCKS];
__device__ int   g_count[BLOCKS];
__device__ unsigned int g_ticket = 0;

__global__ void __launch_bounds__(THREADS, 8)
ord_loss_fused(const float* __restrict__ pred,
               const int*   __restrict__ target,
               const int*   __restrict__ mask,
               float*       __restrict__ out)
{
    const int g = blockIdx.x * THREADS + threadIdx.x;  // group of 4 voxels
    const int m = g * 4;
    const int n = m >> 19;                              // MSP == 2^19
    const int base = m + n * (C_ - 1) * MSP;            // n*C*MSP + spatial

    const int4 mk = *reinterpret_cast<const int4*>(mask + m);
    const int4 tg = *reinterpret_cast<const int4*>(target + base);

    // negated float targets: bias_k = saturate(k + nt)
    const float nt0 = -(float)tg.x;
    const float nt1 = -(float)tg.y;
    const float nt2 = -(float)tg.z;
    const float nt3 = -(float)tg.w;

    // mask folded into per-voxel clip floor: invalid -> floor 1.0 -> log 0
    const float c0 = (mk.x > 0) ? 1e-8f : 1.0f;
    const float c1 = (mk.y > 0) ? 1e-8f : 1.0f;
    const float c2 = (mk.z > 0) ? 1e-8f : 1.0f;
    const float c3 = (mk.w > 0) ? 1e-8f : 1.0f;
    int cnt = (mk.x > 0) + (mk.y > 0) + (mk.z > 0) + (mk.w > 0);

    // ---- cp.async 4-deep per-thread ring through SMEM ----
    __shared__ float4 stage[STAGES][THREADS];           // 16 KB

    const char* gsrc = reinterpret_cast<const char*>(pred + base);
    uint32_t s_addr[STAGES];
#pragma unroll
    for (int s = 0; s < STAGES; ++s)
        s_addr[s] = (uint32_t)__cvta_generic_to_shared(&stage[s][threadIdx.x]);

    // prologue: channels 0..2 in flight
#pragma unroll
    for (int k = 0; k < STAGES - 1; ++k) {
        asm volatile("cp.async.cg.shared.global [%0], [%1], 16;"
                     :: "r"(s_addr[k]), "l"(gsrc + (size_t)k * (MSP * 4)) : "memory");
        asm volatile("cp.async.commit_group;" ::: "memory");
    }

    float acc = 0.0f;

#pragma unroll
    for (int k = 0; k < C_; ++k) {
        if (k + STAGES - 1 < C_) {
            asm volatile("cp.async.cg.shared.global [%0], [%1], 16;"
                         :: "r"(s_addr[(k + STAGES - 1) & (STAGES - 1)]),
                            "l"(gsrc + (size_t)(k + STAGES - 1) * (MSP * 4)) : "memory");
        }
        asm volatile("cp.async.commit_group;" ::: "memory");  // keep group numbering
        asm volatile("cp.async.wait_group %0;" :: "n"(STAGES - 1) : "memory");

        const float4 cur = stage[k & (STAGES - 1)][threadIdx.x];
        const float kf = (float)k;                       // unrolled immediate
        // bias = 0 when k<=t, 1 when k>t; q = |bias - p| = p or 1-p (exact)
        const float q0 = fmaxf(fabsf(__saturatef(kf + nt0) - cur.x), c0);
        const float q1 = fmaxf(fabsf(__saturatef(kf + nt1) - cur.y), c1);
        const float q2 = fmaxf(fabsf(__saturatef(kf + nt2) - cur.z), c2);
        const float q3 = fmaxf(fabsf(__saturatef(kf + nt3) - cur.w), c3);
        acc += __logf((q0 * q1) * (q2 * q3));            // product >= 1e-32
    }

    float a = acc;

    // ---- warp reduce ----
#pragma unroll
    for (int off = 16; off > 0; off >>= 1) {
        a   += __shfl_xor_sync(0xFFFFFFFFu, a, off);
        cnt += __shfl_xor_sync(0xFFFFFFFFu, cnt, off);
    }

    __shared__ float sa[THREADS / 32];
    __shared__ int   sc[THREADS / 32];
    __shared__ bool  s_last;
    const int wid = threadIdx.x >> 5;
    const int lid = threadIdx.x & 31;
    if (lid == 0) { sa[wid] = a; sc[wid] = cnt; }
    __syncthreads();

    if (threadIdx.x == 0) {
        float aa = sa[0] + sa[1] + sa[2] + sa[3] + sa[4] + sa[5] + sa[6] + sa[7];
        int   cc = sc[0] + sc[1] + sc[2] + sc[3] + sc[4] + sc[5] + sc[6] + sc[7];
        asm volatile("st.release.gpu.global.f32 [%0], %1;"
                     :: "l"(&g_partial[blockIdx.x]), "f"(aa) : "memory");
        asm volatile("st.release.gpu.global.b32 [%0], %1;"
                     :: "l"(&g_count[blockIdx.x]), "r"(cc) : "memory");
        unsigned int old;
        asm volatile("atom.acq_rel.gpu.global.add.u32 %0, [%1], %2;"
                     : "=r"(old) : "l"(&g_ticket), "r"(1u) : "memory");
        s_last = (old == BLOCKS - 1);
    }
    __syncthreads();

    if (!s_last) return;

    // ---- last block: final reduction over 1024 partials, fixed order ----
    float s = 0.0f;
    int   c = 0;
#pragma unroll
    for (int i = 0; i < BLOCKS / THREADS; ++i) {
        const int idx = threadIdx.x + i * THREADS;
        s += __ldcg(&g_partial[idx]);
        c += __ldcg(&g_count[idx]);
    }
#pragma unroll
    for (int off = 16; off > 0; off >>= 1) {
        s += __shfl_xor_sync(0xFFFFFFFFu, s, off);
        c += __shfl_xor_sync(0xFFFFFFFFu, c, off);
    }
    __shared__ float fa[THREADS / 32];
    __shared__ int   fc[THREADS / 32];
    if (lid == 0) { fa[wid] = s; fc[wid] = c; }
    __syncthreads();
    if (threadIdx.x == 0) {
        float ss = fa[0] + fa[1] + fa[2] + fa[3] + fa[4] + fa[5] + fa[6] + fa[7];
        int   cc = fc[0] + fc[1] + fc[2] + fc[3] + fc[4] + fc[5] + fc[6] + fc[7];
        out[0] = -ss / (float)cc;
        g_ticket = 0;   // reset for next graph replay
    }
}

extern "C" void kernel_launch(void* const* d_in, const int* in_sizes, int n_in,
                              void* d_out, int out_size)
{
    const float* pred   = (const float*)d_in[0];
    const int*   target = (const int*)d_in[1];
    const int*   mask   = (const int*)d_in[2];
    float*       out    = (float*)d_out;

    ord_loss_fused<<<BLOCKS, THREADS>>>(pred, target, mask, out);
}